// round 1
// baseline (speedup 1.0000x reference)
#include <cuda_runtime.h>
#include <cuda_bf16.h>

// HierarchicalDistanceLoss: B=1048576 rows, C=40 classes.
// out[0] = mean(ce * df) ; out[1..B] = df (distance_factor), when out_size > B.
//
// Kernel 1: 4096 blocks x 256 threads, 256 rows/block.
//   - Stage 256x40 f32 logits tile into smem via fully coalesced float4 loads.
//   - smem row pitch = 41 floats (odd) -> conflict-free per-thread row scans.
//   - Per row: max/argmax, sum(exp(x-m)), ce = m + log(S) - x[label],
//     df = dis[label*40 + argmax] + 0.5, store df, block-reduce ce*df.
// Kernel 2: deterministic reduction of 4096 partials -> out[0] = sum / B.

#define HDL_B 1048576
#define HDL_C 40
#define HDL_BLOCKS 4096
#define HDL_TPB 256
#define HDL_PITCH 41  // 40 + 1 pad, odd -> bank-conflict-free row reads

__device__ float g_hdl_partials[HDL_BLOCKS];

__global__ __launch_bounds__(HDL_TPB) void hdl_main_kernel(
    const float* __restrict__ logits,
    const int* __restrict__ labels,
    const float* __restrict__ dis,
    float* __restrict__ out,
    int df_offset, int store_df)
{
    __shared__ float s[HDL_TPB * HDL_PITCH];   // 256*41*4 = 41984 B
    __shared__ float wsum[HDL_TPB / 32];

    const int tid = threadIdx.x;
    const long long row_base = (long long)blockIdx.x * HDL_TPB;

    // ---- coalesced staged load: 256 rows * 10 float4 each ----
    const float4* g4 = reinterpret_cast<const float4*>(logits) + row_base * (HDL_C / 4);
    #pragma unroll
    for (int k = 0; k < 10; k++) {
        int idx = k * HDL_TPB + tid;          // 0..2559, contiguous across warp
        int row = idx / 10;
        int q   = idx % 10;
        float4 v = __ldg(&g4[idx]);
        float* p = &s[row * HDL_PITCH + q * 4];
        p[0] = v.x; p[1] = v.y; p[2] = v.z; p[3] = v.w;
    }
    __syncthreads();

    // ---- per-thread row compute ----
    const float* x = &s[tid * HDL_PITCH];

    float m = x[0];
    int am = 0;
    #pragma unroll
    for (int c = 1; c < HDL_C; c++) {
        float v = x[c];
        if (v > m) { m = v; am = c; }         // strict '>' keeps FIRST max (argmax semantics)
    }
    float ssum = 0.0f;
    #pragma unroll
    for (int c = 0; c < HDL_C; c++) {
        ssum += __expf(x[c] - m);
    }

    const long long grow = row_base + tid;
    const int lbl = labels[grow];
    const float ce = m + __logf(ssum) - x[lbl];
    const float df = __ldg(&dis[lbl * HDL_C + am]) + 0.5f;

    if (store_df) out[df_offset + grow] = df;

    // ---- deterministic block reduction of ce*df ----
    float val = ce * df;
    #pragma unroll
    for (int o = 16; o > 0; o >>= 1)
        val += __shfl_down_sync(0xFFFFFFFFu, val, o);
    if ((tid & 31) == 0) wsum[tid >> 5] = val;
    __syncthreads();
    if (tid == 0) {
        float acc = 0.0f;
        #pragma unroll
        for (int w = 0; w < HDL_TPB / 32; w++) acc += wsum[w];
        g_hdl_partials[blockIdx.x] = acc;
    }
}

__global__ __launch_bounds__(1024) void hdl_finish_kernel(float* __restrict__ out,
                                                          int write_loss)
{
    __shared__ float s[1024];
    const int tid = threadIdx.x;
    float v = 0.0f;
    #pragma unroll
    for (int i = 0; i < HDL_BLOCKS / 1024; i++)
        v += g_hdl_partials[tid + i * 1024];
    s[tid] = v;
    __syncthreads();
    #pragma unroll
    for (int o = 512; o > 0; o >>= 1) {
        if (tid < o) s[tid] += s[tid + o];
        __syncthreads();
    }
    if (tid == 0 && write_loss)
        out[0] = s[0] * (1.0f / (float)HDL_B);
}

extern "C" void kernel_launch(void* const* d_in, const int* in_sizes, int n_in,
                              void* d_out, int out_size)
{
    const float* logits = (const float*)d_in[0];
    const int*   labels = (const int*)d_in[1];
    const float* dis    = (const float*)d_in[2];
    float* out = (float*)d_out;

    // Layout handling: if out has room for loss + df, loss at [0], df at [1..B].
    const int has_loss = (out_size != HDL_B) ? 1 : 0;
    const int df_off   = (out_size > HDL_B) ? 1 : 0;
    const int store_df = (out_size >= HDL_B) ? 1 : 0;

    hdl_main_kernel<<<HDL_BLOCKS, HDL_TPB>>>(logits, labels, dis, out, df_off, store_df);
    hdl_finish_kernel<<<1, 1024>>>(out, has_loss);
}